// round 2
// baseline (speedup 1.0000x reference)
#include <cuda_runtime.h>
#include <cstdint>

// Problem constants (B=8, C=64, 256x256, P=8)
#define NB   8
#define CIN  64
#define HW   65536     // 256*256
#define NTOK 1024      // (256/8)*(256/8)
#define MDIM 512       // Cq * P * P = 8*64

// ---------------- scratch (allocation-free: __device__ globals) ----------------
__device__ float g_Q[(size_t)NB * NTOK * MDIM];   // Q tokens  [b][n][m]
__device__ float g_K[(size_t)NB * NTOK * MDIM];   // K tokens  [b][n][m]
__device__ float g_V[(size_t)NB * MDIM * NTOK];   // V tokens  [b][m][n]
__device__ float g_E[(size_t)NB * NTOK * NTOK];   // energy -> attn (in place)
__device__ float g_O[(size_t)NB * NTOK * MDIM];   // out, transposed: [b][j][m]

__device__ __forceinline__ float tf32r(float x) {
    uint32_t u;
    asm("cvt.rna.tf32.f32 %0, %1;" : "=r"(u) : "f"(x));
    return __uint_as_float(u);
}

// ---------------- kernel 1: QKV 1x1 conv + unfold permutation ----------------
// pixel (w,h):  wp=w/8, p1=w%8, hp=h/8, p2=h%8
//   m = cq*64 + wp*2 + hp/16        (the non-separable view reshape, replicated exactly)
//   n = (hp%16)*64 + p1*8 + p2
__global__ __launch_bounds__(256) void qkv_proj_kernel(
    const float* __restrict__ x,
    const float* __restrict__ Wq, const float* __restrict__ bq,
    const float* __restrict__ Wk, const float* __restrict__ bk,
    const float* __restrict__ Wv, const float* __restrict__ bv)
{
    __shared__ float sW[24 * 64];
    __shared__ float sB[24];
    int tid = threadIdx.x;
    for (int idx = tid; idx < 24 * 64; idx += 256) {
        int o = idx >> 6, c = idx & 63;
        const float* src = (o < 8) ? Wq : (o < 16) ? Wk : Wv;
        sW[idx] = src[(o & 7) * 64 + c];
    }
    if (tid < 24) {
        const float* src = (tid < 8) ? bq : (tid < 16) ? bk : bv;
        sB[tid] = src[tid & 7];
    }
    __syncthreads();

    int b   = blockIdx.y;
    int pid = blockIdx.x * 256 + tid;       // 0..65535, h fastest -> coalesced
    int w = pid >> 8, h = pid & 255;

    float acc[24];
#pragma unroll
    for (int o = 0; o < 24; o++) acc[o] = sB[o];

    const float* xp = x + (size_t)b * CIN * HW + pid;
#pragma unroll 4
    for (int c = 0; c < 64; c++) {
        float xv = __ldg(xp + (size_t)c * HW);
#pragma unroll
        for (int o = 0; o < 24; o++) acc[o] = fmaf(sW[o * 64 + c], xv, acc[o]);
    }

    int wp = w >> 3, p1 = w & 7, hp = h >> 3, p2 = h & 7;
    int m_off = wp * 2 + (hp >> 4);
    int n = ((hp & 15) << 6) + (p1 << 3) + p2;

    size_t qk = ((size_t)b * NTOK + n) * MDIM + m_off;
    size_t vb = ((size_t)b * MDIM + m_off) * NTOK + n;
#pragma unroll
    for (int q = 0; q < 8; q++) {
        g_Q[qk + q * 64] = tf32r(acc[q]);
        g_K[qk + q * 64] = tf32r(acc[8 + q]);
        g_V[vb + (size_t)q * 64 * NTOK] = tf32r(acc[16 + q]);
    }
}

// ---------------- batched C = A * B^T (tf32 mma.sync), device body ----------------
// A: [I,K] row-major, B: [J,K] row-major, C: [I,J] row-major. Dims multiples of tile.
#define BM 128
#define BN 128
#define BK 16
#define SPAD 20                 // 16 + 4 pad: conflict-free fragment loads
#define STAGE_F (128 * SPAD)

__device__ __forceinline__ void cp16(float* s, const float* g) {
    uint32_t sa = (uint32_t)__cvta_generic_to_shared(s);
    asm volatile("cp.async.ca.shared.global [%0], [%1], 16;" :: "r"(sa), "l"(g));
}

__device__ __forceinline__ void gemm_abt_body(
    const float* __restrict__ A, const float* __restrict__ B, float* __restrict__ C,
    int I, int J, int K)
{
    __shared__ float sm[4 * STAGE_F];     // [2 stages][A|B][128][SPAD] = 40 KB
    float* sA = sm;
    float* sB = sm + 2 * STAGE_F;

    int bz = blockIdx.z;
    A += (size_t)bz * I * K;
    B += (size_t)bz * J * K;
    C += (size_t)bz * I * J;
    int i0 = blockIdx.y * BM, j0 = blockIdx.x * BN;

    int tid = threadIdx.x, warp = tid >> 5, lane = tid & 31;
    int wm = warp >> 2, wn = warp & 3;     // 2x4 warp grid, warp tile 64x32
    int grp = lane >> 2, tig = lane & 3;

    float acc[4][4][4];
#pragma unroll
    for (int a = 0; a < 4; a++)
#pragma unroll
        for (int bb = 0; bb < 4; bb++)
#pragma unroll
            for (int cc = 0; cc < 4; cc++) acc[a][bb][cc] = 0.f;

    int kTiles = K / BK;

    auto loadTile = [&](int stage, int kt) {
        const float* Ag = A + (size_t)i0 * K + kt * BK;
        const float* Bg = B + (size_t)j0 * K + kt * BK;
        float* sa = sA + stage * STAGE_F;
        float* sb = sB + stage * STAGE_F;
#pragma unroll
        for (int s = 0; s < 2; s++) {
            int lin = s * 256 + tid;           // 512 float4 per operand tile
            int row = lin >> 2, c4 = (lin & 3) * 4;
            cp16(sa + row * SPAD + c4, Ag + (size_t)row * K + c4);
            cp16(sb + row * SPAD + c4, Bg + (size_t)row * K + c4);
        }
        asm volatile("cp.async.commit_group;");
    };

    loadTile(0, 0);
    for (int kt = 0; kt < kTiles; kt++) {
        if (kt + 1 < kTiles) {
            loadTile((kt + 1) & 1, kt + 1);
            asm volatile("cp.async.wait_group 1;");
        } else {
            asm volatile("cp.async.wait_group 0;");
        }
        __syncthreads();

        const float* sa = sA + (kt & 1) * STAGE_F;
        const float* sb = sB + (kt & 1) * STAGE_F;
#pragma unroll
        for (int ks = 0; ks < 2; ks++) {
            uint32_t af[4][4];
#pragma unroll
            for (int mt = 0; mt < 4; mt++) {
                const float* p = sa + (wm * 64 + mt * 16 + grp) * SPAD + ks * 8 + tig;
                af[mt][0] = __float_as_uint(p[0]);
                af[mt][1] = __float_as_uint(p[8 * SPAD]);
                af[mt][2] = __float_as_uint(p[4]);
                af[mt][3] = __float_as_uint(p[8 * SPAD + 4]);
            }
#pragma unroll
            for (int nt = 0; nt < 4; nt++) {
                const float* p = sb + (wn * 32 + nt * 8 + grp) * SPAD + ks * 8 + tig;
                uint32_t bf0 = __float_as_uint(p[0]);
                uint32_t bf1 = __float_as_uint(p[4]);
#pragma unroll
                for (int mt = 0; mt < 4; mt++) {
                    asm volatile(
                        "mma.sync.aligned.m16n8k8.row.col.f32.tf32.tf32.f32 "
                        "{%0,%1,%2,%3}, {%4,%5,%6,%7}, {%8,%9}, {%0,%1,%2,%3};"
                        : "+f"(acc[mt][nt][0]), "+f"(acc[mt][nt][1]),
                          "+f"(acc[mt][nt][2]), "+f"(acc[mt][nt][3])
                        : "r"(af[mt][0]), "r"(af[mt][1]), "r"(af[mt][2]), "r"(af[mt][3]),
                          "r"(bf0), "r"(bf1));
                }
            }
        }
        __syncthreads();
    }

#pragma unroll
    for (int mt = 0; mt < 4; mt++)
#pragma unroll
        for (int nt = 0; nt < 4; nt++) {
            int i = i0 + wm * 64 + mt * 16 + grp;
            int j = j0 + wn * 32 + nt * 8 + tig * 2;
            *reinterpret_cast<float2*>(C + (size_t)i * J + j) =
                make_float2(acc[mt][nt][0], acc[mt][nt][1]);
            *reinterpret_cast<float2*>(C + (size_t)(i + 8) * J + j) =
                make_float2(acc[mt][nt][2], acc[mt][nt][3]);
        }
}

// Thin wrappers referencing __device__ globals directly (no symbol-address API on host).
__global__ __launch_bounds__(256) void gemm_qk_kernel() {
    gemm_abt_body(g_Q, g_K, g_E, NTOK, NTOK, MDIM);
}
__global__ __launch_bounds__(256) void gemm_av_kernel() {
    gemm_abt_body(g_E, g_V, g_O, NTOK, MDIM, NTOK);
}

// ---------------- kernel 3: row softmax of E/32, in place, tf32-rounded output ----------------
__global__ __launch_bounds__(256) void softmax_kernel()
{
    __shared__ float redm[8], reds[8];
    int b = blockIdx.y, row = blockIdx.x;
    float4* p = reinterpret_cast<float4*>(g_E + ((size_t)b * NTOK + row) * NTOK);
    int tid = threadIdx.x, lane = tid & 31, warp = tid >> 5;

    float4 v = p[tid];
    const float S = 0.03125f;     // 1/sqrt(1024)
    v.x *= S; v.y *= S; v.z *= S; v.w *= S;

    float mx = fmaxf(fmaxf(v.x, v.y), fmaxf(v.z, v.w));
#pragma unroll
    for (int o = 16; o; o >>= 1) mx = fmaxf(mx, __shfl_xor_sync(0xffffffffu, mx, o));
    if (lane == 0) redm[warp] = mx;
    __syncthreads();
    mx = redm[0];
#pragma unroll
    for (int i = 1; i < 8; i++) mx = fmaxf(mx, redm[i]);

    float e0 = __expf(v.x - mx), e1 = __expf(v.y - mx);
    float e2 = __expf(v.z - mx), e3 = __expf(v.w - mx);
    float s = e0 + e1 + e2 + e3;
#pragma unroll
    for (int o = 16; o; o >>= 1) s += __shfl_xor_sync(0xffffffffu, s, o);
    if (lane == 0) reds[warp] = s;
    __syncthreads();
    s = reds[0];
#pragma unroll
    for (int i = 1; i < 8; i++) s += reds[i];

    float inv = 1.0f / s;
    float4 ov;
    ov.x = tf32r(e0 * inv); ov.y = tf32r(e1 * inv);
    ov.z = tf32r(e2 * inv); ov.w = tf32r(e3 * inv);
    p[tid] = ov;
}

// ---------------- kernel 4: output 1x1 conv + gamma*y + x ----------------
// out_spatial[b,cq,w,h] = O[b, j=cq*128+w/2, m=(w&1)*256+h]  (transposed O layout)
__global__ __launch_bounds__(256) void out_proj_kernel(
    const float* __restrict__ x, const float* __restrict__ Wo,
    const float* __restrict__ bo, const float* __restrict__ gamma,
    float* __restrict__ out)
{
    __shared__ float sWo[64 * 8];
    __shared__ float sBo[64];
    int tid = threadIdx.x;
    for (int i = tid; i < 512; i += 256) sWo[i] = Wo[i];
    if (tid < 64) sBo[tid] = bo[tid];
    __syncthreads();

    float g = __ldg(gamma);
    int b = blockIdx.y;
    int pid = blockIdx.x * 256 + tid;
    int w = pid >> 8, h = pid & 255;
    int m  = ((w & 1) << 8) + h;
    int jb = w >> 1;

    float ov[8];
#pragma unroll
    for (int q = 0; q < 8; q++)
        ov[q] = g_O[((size_t)b * NTOK + q * 128 + jb) * MDIM + m];

    size_t base = (size_t)b * CIN * HW + pid;
#pragma unroll 4
    for (int c = 0; c < 64; c++) {
        float y = sBo[c];
#pragma unroll
        for (int q = 0; q < 8; q++) y = fmaf(sWo[c * 8 + q], ov[q], y);
        size_t idx = base + (size_t)c * HW;
        out[idx] = fmaf(g, y, __ldg(x + idx));
    }
}

// ---------------- launch: kernel launches ONLY ----------------
extern "C" void kernel_launch(void* const* d_in, const int* in_sizes, int n_in,
                              void* d_out, int out_size)
{
    const float* x     = (const float*)d_in[0];
    const float* Wq    = (const float*)d_in[1];
    const float* bq    = (const float*)d_in[2];
    const float* Wk    = (const float*)d_in[3];
    const float* bk    = (const float*)d_in[4];
    const float* Wv    = (const float*)d_in[5];
    const float* bv    = (const float*)d_in[6];
    const float* Wo    = (const float*)d_in[7];
    const float* bo    = (const float*)d_in[8];
    const float* gamma = (const float*)d_in[9];
    float* out = (float*)d_out;

    // 1. QKV projection + patch-token permutation
    qkv_proj_kernel<<<dim3(256, NB), 256>>>(x, Wq, bq, Wk, bk, Wv, bv);
    // 2. E = Q * K^T   (I=1024, J=1024, K=512)
    gemm_qk_kernel<<<dim3(NTOK / BN, NTOK / BM, NB), 256>>>();
    // 3. attn = softmax(E / 32), in place
    softmax_kernel<<<dim3(NTOK, NB), 256>>>();
    // 4. O^T = attn * V^T  (I=1024, J=512, K=1024)
    gemm_av_kernel<<<dim3(MDIM / BN, NTOK / BM, NB), 256>>>();
    // 5. output projection + residual
    out_proj_kernel<<<dim3(256, NB), 256>>>(x, Wo, bo, gamma, out);
}

// round 7
// speedup vs baseline: 1.2278x; 1.2278x over previous
#include <cuda_runtime.h>
#include <cuda_bf16.h>
#include <cstdint>

// Problem constants (B=8, C=64, 256x256, P=8)
#define NB   8
#define CIN  64
#define HW   65536
#define NTOK 1024
#define MDIM 512

// ---------------- scratch (__device__ globals; no allocation) ----------------
__device__ __nv_bfloat16 g_Qh[(size_t)NB * NTOK * MDIM];  // [b][n][m]
__device__ __nv_bfloat16 g_Kh[(size_t)NB * NTOK * MDIM];  // [b][n'][m]
__device__ __nv_bfloat16 g_Vh[(size_t)NB * MDIM * NTOK];  // [b][m][n']
__device__ float         g_E [(size_t)NB * NTOK * NTOK];  // energy fp32
__device__ __nv_bfloat16 g_Ah[(size_t)NB * NTOK * NTOK];  // attn bf16 [b][n][n']
__device__ float         g_O [(size_t)NB * NTOK * MDIM];  // [b][token][m] fp32

// ================= kernel 1: QKV 1x1 conv + patch-token permutation =================
// pixel (w,h): wp=w>>3, p1=w&7, hp=h>>3, p2=h&7
//   m = cq*64 + wp*2 + (hp>>4)     n = (hp&15)*64 + p1*8 + p2
// Block: wp0=bx*4, hp0=by, b=bz; 512 threads, tid = wpl(2)<<7 | c<<6 | p1(3)<<3 | p2(3)
// covers n in [hp0*64,+64) and per-cq m in [cq*64+wp0*2,+8).
__global__ __launch_bounds__(512) void qkv_kernel(
    const float* __restrict__ x,
    const float* __restrict__ Wq, const float* __restrict__ bq,
    const float* __restrict__ Wk, const float* __restrict__ bk,
    const float* __restrict__ Wv, const float* __restrict__ bv)
{
    __shared__ float sW[24 * 64];
    __shared__ float sB[24];
    __shared__ float tile[2][64 * 69];   // Q,K staging: [arr][nl*69 + cq*8 + ml]

    int tid = threadIdx.x;
    for (int idx = tid; idx < 24 * 64; idx += 512) {
        int o = idx >> 6, ch = idx & 63;
        const float* src = (o < 8) ? Wq : (o < 16) ? Wk : Wv;
        sW[idx] = src[(o & 7) * 64 + ch];
    }
    if (tid < 24) {
        const float* src = (tid < 8) ? bq : (tid < 16) ? bk : bv;
        sB[tid] = src[tid & 7];
    }
    __syncthreads();

    int b = blockIdx.z, hp0 = blockIdx.y, wp0 = blockIdx.x * 4;
    int wpl = tid >> 7, c = (tid >> 6) & 1, p1 = (tid >> 3) & 7, p2 = tid & 7;
    int w = (wp0 + wpl) * 8 + p1;
    int h = (hp0 + c * 16) * 8 + p2;
    int pid = (w << 8) + h;

    float acc[24];
#pragma unroll
    for (int o = 0; o < 24; o++) acc[o] = sB[o];

    const float* xp = x + (size_t)b * CIN * HW + pid;
#pragma unroll 4
    for (int ch = 0; ch < 64; ch++) {
        float xv = __ldg(xp + (size_t)ch * HW);
#pragma unroll
        for (int o = 0; o < 24; o++) acc[o] = fmaf(sW[o * 64 + ch], xv, acc[o]);
    }

    // ---- V: direct coalesced store, layout [b][m][n'] ----
    int n = hp0 * 64 + p1 * 8 + p2;
    int mv = (wp0 + wpl) * 2 + c;              // m = cq*64 + mv
    size_t vrow = ((size_t)b * MDIM + mv) * NTOK + n;
#pragma unroll
    for (int cq = 0; cq < 8; cq++)
        g_Vh[vrow + (size_t)cq * 64 * NTOK] = __float2bfloat16(acc[16 + cq]);

    // ---- Q,K: smem-staged transpose, layout [b][n][m] ----
    int nl = tid & 63;          // p1*8+p2
    int ml = tid >> 6;          // wpl*2 + c
#pragma unroll
    for (int a = 0; a < 2; a++)
#pragma unroll
        for (int cq = 0; cq < 8; cq++)
            tile[a][nl * 69 + cq * 8 + ml] = acc[a * 8 + cq];
    __syncthreads();

    int nl2 = tid >> 3, ml2 = tid & 7;
    size_t qbase = ((size_t)b * NTOK + hp0 * 64 + nl2) * MDIM + wp0 * 2 + ml2;
#pragma unroll
    for (int cq = 0; cq < 8; cq++) {
        g_Qh[qbase + cq * 64] = __float2bfloat16(tile[0][nl2 * 69 + cq * 8 + ml2]);
        g_Kh[qbase + cq * 64] = __float2bfloat16(tile[1][nl2 * 69 + cq * 8 + ml2]);
    }
}

// ================= bf16 GEMM: C = A * B^T =================
// A: [I,Kd] bf16, B: [J,Kd] bf16, C: [I,J] fp32.  Tiles 128x128x16, 3-stage cp.async.
#define GP 24                       // smem pitch in halves (12 words; bank-spread verified)

__device__ __forceinline__ void cp16(void* s, const void* g) {
    uint32_t sa = (uint32_t)__cvta_generic_to_shared(s);
    asm volatile("cp.async.ca.shared.global [%0], [%1], 16;" :: "r"(sa), "l"(g));
}
template <int N> __device__ __forceinline__ void cpwait() {
    asm volatile("cp.async.wait_group %0;" :: "n"(N));
}

__device__ __forceinline__ void gemm_bf16_body(
    const __nv_bfloat16* __restrict__ A, const __nv_bfloat16* __restrict__ B,
    float* __restrict__ C, int I, int J, int Kd)
{
    __shared__ __nv_bfloat16 sm[3][2][128 * GP];   // 36.9 KB

    int bz = blockIdx.z;
    A += (size_t)bz * I * Kd;
    B += (size_t)bz * J * Kd;
    C += (size_t)bz * I * J;
    int i0 = blockIdx.y * 128, j0 = blockIdx.x * 128;

    int tid = threadIdx.x, warp = tid >> 5, lane = tid & 31;
    int wm = warp >> 2, wn = warp & 3;      // 2x4 warps, warp tile 64x32
    int grp = lane >> 2, tig = lane & 3;

    float acc[4][4][4];
#pragma unroll
    for (int a = 0; a < 4; a++)
#pragma unroll
        for (int bb = 0; bb < 4; bb++)
#pragma unroll
            for (int cc = 0; cc < 4; cc++) acc[a][bb][cc] = 0.f;

    int kT = Kd / 16;

    // 128x16-half tile = 256 x 16B chunks per operand; 256 threads -> 1 chunk each.
    int lrow = tid >> 1, lch = (tid & 1) * 8;
    auto loadTile = [&](int stage, int kt) {
        const __nv_bfloat16* Ag = A + (size_t)i0 * Kd + kt * 16;
        const __nv_bfloat16* Bg = B + (size_t)j0 * Kd + kt * 16;
        cp16(&sm[stage][0][lrow * GP + lch], Ag + (size_t)lrow * Kd + lch);
        cp16(&sm[stage][1][lrow * GP + lch], Bg + (size_t)lrow * Kd + lch);
        asm volatile("cp.async.commit_group;");
    };

    loadTile(0, 0);
    loadTile(1, 1);
    cpwait<1>();
    __syncthreads();

    for (int kt = 0; kt < kT; kt++) {
        int cur = kt % 3;
        if (kt + 2 < kT) loadTile((kt + 2) % 3, kt + 2);

        const uint32_t* wA = (const uint32_t*)sm[cur][0];
        const uint32_t* wB = (const uint32_t*)sm[cur][1];

        uint32_t aw[4][4];
#pragma unroll
        for (int mt = 0; mt < 4; mt++) {
            int r = wm * 64 + mt * 16 + grp;
            aw[mt][0] = wA[r * 12 + tig];
            aw[mt][1] = wA[(r + 8) * 12 + tig];
            aw[mt][2] = wA[r * 12 + tig + 4];
            aw[mt][3] = wA[(r + 8) * 12 + tig + 4];
        }
#pragma unroll
        for (int nt = 0; nt < 4; nt++) {
            int jr = wn * 32 + nt * 8 + grp;
            uint32_t bw0 = wB[jr * 12 + tig];
            uint32_t bw1 = wB[jr * 12 + tig + 4];
#pragma unroll
            for (int mt = 0; mt < 4; mt++) {
                asm volatile(
                    "mma.sync.aligned.m16n8k16.row.col.f32.bf16.bf16.f32 "
                    "{%0,%1,%2,%3}, {%4,%5,%6,%7}, {%8,%9}, {%0,%1,%2,%3};"
                    : "+f"(acc[mt][nt][0]), "+f"(acc[mt][nt][1]),
                      "+f"(acc[mt][nt][2]), "+f"(acc[mt][nt][3])
                    : "r"(aw[mt][0]), "r"(aw[mt][1]), "r"(aw[mt][2]), "r"(aw[mt][3]),
                      "r"(bw0), "r"(bw1));
            }
        }

        if (kt + 2 < kT)      cpwait<1>();
        else if (kt + 1 < kT) cpwait<0>();
        __syncthreads();
    }

#pragma unroll
    for (int mt = 0; mt < 4; mt++)
#pragma unroll
        for (int nt = 0; nt < 4; nt++) {
            int i = i0 + wm * 64 + mt * 16 + grp;
            int j = j0 + wn * 32 + nt * 8 + tig * 2;
            *reinterpret_cast<float2*>(C + (size_t)i * J + j) =
                make_float2(acc[mt][nt][0], acc[mt][nt][1]);
            *reinterpret_cast<float2*>(C + (size_t)(i + 8) * J + j) =
                make_float2(acc[mt][nt][2], acc[mt][nt][3]);
        }
}

__global__ __launch_bounds__(256, 2) void gemm_qk_kernel() {
    gemm_bf16_body(g_Qh, g_Kh, g_E, NTOK, NTOK, MDIM);
}
__global__ __launch_bounds__(256, 2) void gemm_av_kernel() {
    gemm_bf16_body(g_Ah, g_Vh, g_O, NTOK, MDIM, NTOK);
}

// ================= kernel 3: softmax(E/32) -> bf16 attn =================
__global__ __launch_bounds__(256) void softmax_kernel()
{
    __shared__ float redm[8], reds[8];
    int b = blockIdx.y, row = blockIdx.x;
    const float4* p = reinterpret_cast<const float4*>(g_E + ((size_t)b * NTOK + row) * NTOK);
    int tid = threadIdx.x, lane = tid & 31, warp = tid >> 5;

    float4 v = p[tid];
    const float S = 0.03125f;       // 1/sqrt(1024)
    v.x *= S; v.y *= S; v.z *= S; v.w *= S;

    float mx = fmaxf(fmaxf(v.x, v.y), fmaxf(v.z, v.w));
#pragma unroll
    for (int o = 16; o; o >>= 1) mx = fmaxf(mx, __shfl_xor_sync(0xffffffffu, mx, o));
    if (lane == 0) redm[warp] = mx;
    __syncthreads();
    mx = redm[0];
#pragma unroll
    for (int i = 1; i < 8; i++) mx = fmaxf(mx, redm[i]);

    float e0 = __expf(v.x - mx), e1 = __expf(v.y - mx);
    float e2 = __expf(v.z - mx), e3 = __expf(v.w - mx);
    float s = e0 + e1 + e2 + e3;
#pragma unroll
    for (int o = 16; o; o >>= 1) s += __shfl_xor_sync(0xffffffffu, s, o);
    if (lane == 0) reds[warp] = s;
    __syncthreads();
    s = reds[0];
#pragma unroll
    for (int i = 1; i < 8; i++) s += reds[i];

    float inv = 1.0f / s;
    __nv_bfloat162 o01(__float2bfloat16(e0 * inv), __float2bfloat16(e1 * inv));
    __nv_bfloat162 o23(__float2bfloat16(e2 * inv), __float2bfloat16(e3 * inv));
    float2 pk;
    pk.x = __uint_as_float(*reinterpret_cast<uint32_t*>(&o01));
    pk.y = __uint_as_float(*reinterpret_cast<uint32_t*>(&o23));
    reinterpret_cast<float2*>(g_Ah + ((size_t)b * NTOK + row) * NTOK)[tid] = pk;
}

// ================= kernel 4: output 1x1 conv + gamma*y + x =================
// out[b,cq,w,h] = gamma * (Wo . O[b, cq*128+(w>>1), ((w&1)<<8)+h] + bo) + x
__global__ __launch_bounds__(256) void out_proj_kernel(
    const float* __restrict__ x, const float* __restrict__ Wo,
    const float* __restrict__ bo, const float* __restrict__ gamma,
    float* __restrict__ out)
{
    __shared__ float sWo[64 * 8];
    __shared__ float sBo[64];
    int tid = threadIdx.x;
    for (int i = tid; i < 512; i += 256) sWo[i] = Wo[i];
    if (tid < 64) sBo[tid] = bo[tid];
    __syncthreads();

    float g = __ldg(gamma);
    int b = blockIdx.y;
    int pid = blockIdx.x * 256 + tid;
    int w = pid >> 8, h = pid & 255;
    int m  = ((w & 1) << 8) + h;
    int jb = w >> 1;

    float ov[8];
#pragma unroll
    for (int q = 0; q < 8; q++)
        ov[q] = g_O[((size_t)b * NTOK + q * 128 + jb) * MDIM + m];

    size_t base = (size_t)b * CIN * HW + pid;
#pragma unroll 4
    for (int c = 0; c < 64; c++) {
        float y = sBo[c];
#pragma unroll
        for (int q = 0; q < 8; q++) y = fmaf(sWo[c * 8 + q], ov[q], y);
        size_t idx = base + (size_t)c * HW;
        out[idx] = fmaf(g, y, __ldg(x + idx));
    }
}

// ================= launch: kernel launches only =================
extern "C" void kernel_launch(void* const* d_in, const int* in_sizes, int n_in,
                              void* d_out, int out_size)
{
    const float* x     = (const float*)d_in[0];
    const float* Wq    = (const float*)d_in[1];
    const float* bq    = (const float*)d_in[2];
    const float* Wk    = (const float*)d_in[3];
    const float* bk    = (const float*)d_in[4];
    const float* Wv    = (const float*)d_in[5];
    const float* bv    = (const float*)d_in[6];
    const float* Wo    = (const float*)d_in[7];
    const float* bo    = (const float*)d_in[8];
    const float* gamma = (const float*)d_in[9];
    float* out = (float*)d_out;

    qkv_kernel<<<dim3(8, 16, NB), 512>>>(x, Wq, bq, Wk, bk, Wv, bv);
    gemm_qk_kernel<<<dim3(8, 8, NB), 256>>>();
    softmax_kernel<<<dim3(NTOK, NB), 256>>>();
    gemm_av_kernel<<<dim3(4, 8, NB), 256>>>();
    out_proj_kernel<<<dim3(256, NB), 256>>>(x, Wo, bo, gamma, out);
}